// round 4
// baseline (speedup 1.0000x reference)
#include <cuda_runtime.h>
#include <cstdint>

#define N_ROWS   65536
#define DIM      256
#define NCODES   512
#define ND       16777216       // N_ROWS*DIM

typedef unsigned long long ull;

// ---------------- device scratch (no allocations allowed) ----------------
__device__ int   g_idx[N_ROWS];
__device__ float g_cn2[NCODES];            // 0.5*|c|^2
__device__ float g_cout[NCODES * DIM];     // codebook @ W_out^T
__device__ float g_partial[1024];          // per-CTA loss partials
__device__ int   g_mask_mode;              // 0=byte bool, 1=int32, 2=float32

// smem layout (floats) for k_main:
//  zs  [256][68]  @ 0       dim-major z: zs[e*68 + r]          17408
//  Hs  [32][68]   @ 17408   phase A rows, kk-major              2176
//  Ws  [32][258]  @ 19584   phase A W cols, kk-major            8256
//  (Cs [32][130]  @ 17408   phase B codes — aliases dead Hs+Ws, 4160)
//  rowz2[64]      @ 27840
//  lred [16]      @ 27904
#define SM_ZS     0
#define SM_HS     17408
#define SM_WS     19584
#define SM_ROWZ2  27840
#define SM_LRED   27904
#define SM_FLOATS 27920
#define SM_BYTES  (SM_FLOATS * 4)

// ---- packed fp32x2 helpers (FFMA2 reachable only via PTX fma.rn.f32x2) ----
__device__ __forceinline__ ull pk2(float f) {
    ull d; asm("mov.b64 %0, {%1, %1};" : "=l"(d) : "f"(f)); return d;
}
__device__ __forceinline__ void fma2(ull& d, ull a, ull b) {
    asm("fma.rn.f32x2 %0, %1, %2, %0;" : "+l"(d) : "l"(a), "l"(b));
}
__device__ __forceinline__ void upk(ull v, float& lo, float& hi) {
    asm("mov.b64 {%0, %1}, %2;" : "=f"(lo), "=f"(hi) : "l"(v));
}

// ---------------------------------------------------------------------------
// Detect active_mask storage dtype from its byte pattern (first 64KB = the
// smallest candidate buffer size, so always in-bounds). Deterministic.
//   int32 0/1   -> nonzero bytes only at offset%4==0
//   float32 0/1 -> nonzero bytes only 0x80 @%4==2, 0x3F @%4==3
//   else        -> 1-byte bool
// ---------------------------------------------------------------------------
__global__ void k_detect(const unsigned char* __restrict__ p) {
    __shared__ int fl[6];
    int t = threadIdx.x;
    if (t < 6) fl[t] = 0;
    __syncthreads();
    int f0 = 0, f1 = 0, f2 = 0, f2x = 0, f3 = 0, f3x = 0;
    const unsigned int* pu = (const unsigned int*)p;
    for (int k = 0; k < 64; ++k) {
        unsigned int u = pu[t * 64 + k];
        unsigned int b0 = u & 0xFFu, b1 = (u >> 8) & 0xFFu;
        unsigned int b2 = (u >> 16) & 0xFFu, b3 = (u >> 24) & 0xFFu;
        f0 |= (b0 != 0u);
        f1 |= (b1 != 0u);
        f2 |= (b2 != 0u);
        f2x |= (b2 != 0u && b2 != 0x80u);
        f3 |= (b3 != 0u);
        f3x |= (b3 != 0u && b3 != 0x3Fu);
    }
    if (f0)  atomicOr(&fl[0], 1);
    if (f1)  atomicOr(&fl[1], 1);
    if (f2)  atomicOr(&fl[2], 1);
    if (f2x) atomicOr(&fl[3], 1);
    if (f3)  atomicOr(&fl[4], 1);
    if (f3x) atomicOr(&fl[5], 1);
    __syncthreads();
    if (t == 0) {
        int mode;
        if (!fl[1] && !fl[2] && !fl[4])                mode = 1;  // int32 0/1
        else if (!fl[0] && !fl[1] && !fl[3] && !fl[5]) mode = 2;  // float32 0/1
        else                                           mode = 0;  // byte bool
        g_mask_mode = mode;
    }
}

// ---------------------------------------------------------------------------
// g_cn2[c] = 0.5*|codebook[c]|^2   (one warp per code; 64 blocks x 8 warps)
// ---------------------------------------------------------------------------
__global__ void k_cn2(const float* __restrict__ cb) {
    int wid = threadIdx.x >> 5, ln = threadIdx.x & 31;
    int code = blockIdx.x * 8 + wid;
    const float4* r = (const float4*)(cb + (size_t)code * DIM);
    float4 a = r[ln], b = r[ln + 32];
    float s = a.x * a.x + a.y * a.y + a.z * a.z + a.w * a.w
            + b.x * b.x + b.y * b.y + b.z * b.z + b.w * b.w;
    #pragma unroll
    for (int off = 16; off; off >>= 1) s += __shfl_xor_sync(0xFFFFFFFFu, s, off);
    if (ln == 0) g_cn2[code] = 0.5f * s;
}

// ---------------------------------------------------------------------------
// Main fused kernel (FFMA2 microkernel).
// Blocks [0,1024): 64-row VQ tiles: z = H@W_in^T kept entirely in smem,
//   512-code argmax of (z.c - 0.5|c|^2), per-row idx + deterministic
//   fixed-order loss partial (|z-c*|^2 = |z|^2 - 2*best).
// Blocks [1024,1032): C_out = codebook @ W_out^T (same microkernel),
//   exploiting that the straight-through forward value is exactly z_q.
// Thread map (rb=t/16, ec=t%16): rows rb*4..+3; col pairs e = 2*ec+32*p.
// ---------------------------------------------------------------------------
__global__ void __launch_bounds__(256, 2)
k_main(const float* __restrict__ hidden, const float* __restrict__ codebook,
       const float* __restrict__ Win, const float* __restrict__ Wout)
{
    extern __shared__ float sm[];
    float* zs    = sm + SM_ZS;
    float* Hs    = sm + SM_HS;
    float* Ws    = sm + SM_WS;
    float* Cs    = sm + SM_HS;     // phase-B alias (Hs+Ws dead then)
    float* rowz2 = sm + SM_ROWZ2;
    float* lred  = sm + SM_LRED;

    const int t   = threadIdx.x;
    const int rb  = t >> 4;
    const int ec  = t & 15;
    const int rb4 = rb << 2;
    const bool isVQ = (blockIdx.x < 1024);

    const float* src;
    const float* Wm;
    int n0;
    if (isVQ) { n0 = blockIdx.x * 64;          src = hidden   + (size_t)n0 * DIM; Wm = Win;  }
    else      { n0 = (blockIdx.x - 1024) * 64; src = codebook + (size_t)n0 * DIM; Wm = Wout; }

    ull accA[4][8];
    #pragma unroll
    for (int i = 0; i < 4; ++i)
        #pragma unroll
        for (int p = 0; p < 8; ++p) accA[i][p] = 0ull;

    // ---------------- Phase A: z[64][256] = SRC @ Wm^T ----------------
    for (int dk = 0; dk < 8; ++dk) {
        __syncthreads();
        #pragma unroll
        for (int i = 0; i < 2; ++i) {              // Hs: 64 rows x 32 dims, kk-major
            int id = i * 256 + t, r = id >> 3, kg = id & 7;
            float4 v = *(const float4*)(src + (size_t)r * DIM + dk * 32 + kg * 4);
            Hs[(kg * 4 + 0) * 68 + r] = v.x;
            Hs[(kg * 4 + 1) * 68 + r] = v.y;
            Hs[(kg * 4 + 2) * 68 + r] = v.z;
            Hs[(kg * 4 + 3) * 68 + r] = v.w;
        }
        #pragma unroll
        for (int i = 0; i < 8; ++i) {              // Ws: 256 cols x 32 dims, kk-major
            int id = i * 256 + t, e = id >> 3, kg = id & 7;
            float4 v = *(const float4*)(Wm + (size_t)e * DIM + dk * 32 + kg * 4);
            Ws[(kg * 4 + 0) * 258 + e] = v.x;
            Ws[(kg * 4 + 1) * 258 + e] = v.y;
            Ws[(kg * 4 + 2) * 258 + e] = v.z;
            Ws[(kg * 4 + 3) * 258 + e] = v.w;
        }
        __syncthreads();
        #pragma unroll 4
        for (int kk = 0; kk < 32; ++kk) {
            float4 h4 = *(const float4*)(Hs + kk * 68 + rb4);   // broadcast, CF
            ull hz0 = pk2(h4.x), hz1 = pk2(h4.y), hz2 = pk2(h4.z), hz3 = pk2(h4.w);
            const float* wr = Ws + kk * 258 + 2 * ec;           // LDS.64, CF
            #pragma unroll
            for (int p = 0; p < 8; ++p) {
                ull wp = *(const ull*)(wr + 32 * p);
                fma2(accA[0][p], hz0, wp);
                fma2(accA[1][p], hz1, wp);
                fma2(accA[2][p], hz2, wp);
                fma2(accA[3][p], hz3, wp);
            }
        }
    }

    if (!isVQ) {  // C_out blocks: float2 stores, then exit
        #pragma unroll
        for (int p = 0; p < 8; ++p) {
            int e = 2 * ec + 32 * p;
            #pragma unroll
            for (int i = 0; i < 4; ++i) {
                float lo, hi; upk(accA[i][p], lo, hi);
                *(float2*)(g_cout + (size_t)(n0 + rb4 + i) * DIM + e) = make_float2(lo, hi);
            }
        }
        return;
    }

    // transpose-write z to smem (dim-major, stride 68; once per CTA, cheap)
    #pragma unroll
    for (int p = 0; p < 8; ++p) {
        int e = 2 * ec + 32 * p;
        #pragma unroll
        for (int i = 0; i < 4; ++i) {
            float lo, hi; upk(accA[i][p], lo, hi);
            zs[(e    ) * 68 + rb4 + i] = lo;
            zs[(e + 1) * 68 + rb4 + i] = hi;
        }
    }
    __syncthreads();

    // rowz2[r] = |z_r|^2  (4 threads per row, fixed-order reduce)
    {
        int row = t >> 2, part = t & 3;
        float s = 0.0f;
        #pragma unroll 8
        for (int j = 0; j < 64; ++j) {
            float v = zs[(part * 64 + j) * 68 + row];
            s = fmaf(v, v, s);
        }
        s += __shfl_xor_sync(0xFFFFFFFFu, s, 1);
        s += __shfl_xor_sync(0xFFFFFFFFu, s, 2);
        if (part == 0) rowz2[row] = s;
    }

    // ---------------- Phase B: score 512 codes in 4 chunks of 128 ----------------
    float best[4];
    int   bidx[4];
    #pragma unroll
    for (int i = 0; i < 4; ++i) { best[i] = -3.0e38f; bidx[i] = 0; }

    for (int ch = 0; ch < 4; ++ch) {
        const int c0 = ch * 128;
        ull acc2[4][4];
        #pragma unroll
        for (int i = 0; i < 4; ++i)
            #pragma unroll
            for (int p = 0; p < 4; ++p) acc2[i][p] = 0ull;

        for (int dk = 0; dk < 8; ++dk) {
            __syncthreads();
            #pragma unroll
            for (int i = 0; i < 4; ++i) {          // Cs: 128 codes x 32 dims, kk-major
                int id = i * 256 + t, c = id >> 3, kg = id & 7;
                float4 v = *(const float4*)(codebook + (size_t)(c0 + c) * DIM + dk * 32 + kg * 4);
                Cs[(kg * 4 + 0) * 130 + c] = v.x;
                Cs[(kg * 4 + 1) * 130 + c] = v.y;
                Cs[(kg * 4 + 2) * 130 + c] = v.z;
                Cs[(kg * 4 + 3) * 130 + c] = v.w;
            }
            __syncthreads();
            #pragma unroll 4
            for (int kk = 0; kk < 32; ++kk) {
                float4 z4 = *(const float4*)(zs + (dk * 32 + kk) * 68 + rb4);  // broadcast
                ull zz0 = pk2(z4.x), zz1 = pk2(z4.y), zz2 = pk2(z4.z), zz3 = pk2(z4.w);
                const float* cr = Cs + kk * 130 + 2 * ec;                       // LDS.64, CF
                #pragma unroll
                for (int p = 0; p < 4; ++p) {
                    ull cp = *(const ull*)(cr + 32 * p);
                    fma2(acc2[0][p], zz0, cp);
                    fma2(acc2[1][p], zz1, cp);
                    fma2(acc2[2][p], zz2, cp);
                    fma2(acc2[3][p], zz3, cp);
                }
            }
        }
        #pragma unroll
        for (int p = 0; p < 4; ++p) {
            int c = c0 + 2 * ec + 32 * p;
            float hc0 = g_cn2[c], hc1 = g_cn2[c + 1];
            #pragma unroll
            for (int i = 0; i < 4; ++i) {
                float lo, hi; upk(acc2[i][p], lo, hi);
                float s0 = lo - hc0;                 // z.c - 0.5|c|^2
                float s1 = hi - hc1;
                if (s0 > best[i] || (s0 == best[i] && c < bidx[i]))       { best[i] = s0; bidx[i] = c; }
                if (s1 > best[i] || (s1 == best[i] && (c + 1) < bidx[i])) { best[i] = s1; bidx[i] = c + 1; }
            }
        }
    }

    // half-warp (width 16) argmax reduce across ec; lower index wins ties
    #pragma unroll
    for (int i = 0; i < 4; ++i) {
        float s = best[i]; int ix = bidx[i];
        #pragma unroll
        for (int off = 8; off; off >>= 1) {
            float so = __shfl_down_sync(0xFFFFFFFFu, s, off, 16);
            int   io = __shfl_down_sync(0xFFFFFFFFu, ix, off, 16);
            if (so > s || (so == s && io < ix)) { s = so; ix = io; }
        }
        best[i] = s; bidx[i] = ix;
    }

    if (ec == 0) {
        float lsum = 0.0f;
        #pragma unroll
        for (int i = 0; i < 4; ++i) {
            int row = rb4 + i;
            g_idx[n0 + row] = bidx[i];
            lsum += rowz2[row] - 2.0f * best[i];   // |z - c*|^2 for the row
        }
        lred[rb] = lsum;
    }
    __syncthreads();
    if (t == 0) {
        float s = 0.0f;
        #pragma unroll
        for (int j = 0; j < 16; ++j) s += lred[j];  // fixed order -> deterministic
        g_partial[blockIdx.x] = s;
    }
}

// ---------------------------------------------------------------------------
// Loss reduction: loss = 1.25 * sum(partials) / (N*D). Deterministic tree.
// ---------------------------------------------------------------------------
__global__ void k_loss(float* __restrict__ out, int has_loss) {
    __shared__ float red[256];
    int t = threadIdx.x;
    float s = g_partial[t] + g_partial[t + 256] + g_partial[t + 512] + g_partial[t + 768];
    red[t] = s;
    __syncthreads();
    for (int off = 128; off; off >>= 1) {
        if (t < off) red[t] += red[t + off];
        __syncthreads();
    }
    if (t == 0 && has_loss) out[ND] = 1.25f * red[0] / (float)ND;
}

// ---------------------------------------------------------------------------
// Epilogue: h = hidden + mask*C_out[idx]; LayerNorm. One warp per row.
// ---------------------------------------------------------------------------
__global__ void __launch_bounds__(256)
k_pass2(const float* __restrict__ hidden, const void* __restrict__ maskp,
        const float* __restrict__ gamma, const float* __restrict__ beta,
        float* __restrict__ out)
{
    int w = threadIdx.x >> 5, ln = threadIdx.x & 31;
    int n = blockIdx.x * 8 + w;
    int code = g_idx[n];
    int mode = g_mask_mode;
    float m;
    if (mode == 1)      m = ((const int*)maskp)[n] ? 1.0f : 0.0f;
    else if (mode == 2) m = ((const float*)maskp)[n];
    else                m = ((const unsigned char*)maskp)[n] ? 1.0f : 0.0f;

    const float4* hr = (const float4*)(hidden + (size_t)n * DIM);
    const float4* cr = (const float4*)(g_cout + (size_t)code * DIM);
    float4 h0 = hr[ln],      h1 = hr[ln + 32];
    float4 c0 = cr[ln],      c1 = cr[ln + 32];
    h0.x = fmaf(m, c0.x, h0.x); h0.y = fmaf(m, c0.y, h0.y);
    h0.z = fmaf(m, c0.z, h0.z); h0.w = fmaf(m, c0.w, h0.w);
    h1.x = fmaf(m, c1.x, h1.x); h1.y = fmaf(m, c1.y, h1.y);
    h1.z = fmaf(m, c1.z, h1.z); h1.w = fmaf(m, c1.w, h1.w);

    float sum = h0.x + h0.y + h0.z + h0.w + h1.x + h1.y + h1.z + h1.w;
    #pragma unroll
    for (int off = 16; off; off >>= 1) sum += __shfl_xor_sync(0xFFFFFFFFu, sum, off);
    float mu = sum * (1.0f / 256.0f);

    float d0 = h0.x - mu, d1 = h0.y - mu, d2 = h0.z - mu, d3 = h0.w - mu;
    float d4 = h1.x - mu, d5 = h1.y - mu, d6 = h1.z - mu, d7 = h1.w - mu;
    float vs = d0*d0 + d1*d1 + d2*d2 + d3*d3 + d4*d4 + d5*d5 + d6*d6 + d7*d7;
    #pragma unroll
    for (int off = 16; off; off >>= 1) vs += __shfl_xor_sync(0xFFFFFFFFu, vs, off);
    float inv = rsqrtf(vs * (1.0f / 256.0f) + 1e-5f);

    float4 g0 = ((const float4*)gamma)[ln], g1 = ((const float4*)gamma)[ln + 32];
    float4 b0 = ((const float4*)beta)[ln],  b1 = ((const float4*)beta)[ln + 32];
    float4 o0 = make_float4(fmaf(d0 * inv, g0.x, b0.x), fmaf(d1 * inv, g0.y, b0.y),
                            fmaf(d2 * inv, g0.z, b0.z), fmaf(d3 * inv, g0.w, b0.w));
    float4 o1 = make_float4(fmaf(d4 * inv, g1.x, b1.x), fmaf(d5 * inv, g1.y, b1.y),
                            fmaf(d6 * inv, g1.z, b1.z), fmaf(d7 * inv, g1.w, b1.w));
    float4* orow = (float4*)(out + (size_t)n * DIM);
    orow[ln]      = o0;
    orow[ln + 32] = o1;
}

// ---------------------------------------------------------------------------
extern "C" void kernel_launch(void* const* d_in, const int* in_sizes, int n_in,
                              void* d_out, int out_size) {
    const float* hidden   = (const float*)d_in[0];
    const void*  mask     = d_in[1];
    const float* codebook = (const float*)d_in[2];
    const float* Win      = (const float*)d_in[3];
    const float* Wout     = (const float*)d_in[4];
    const float* gamma    = (const float*)d_in[5];
    const float* beta     = (const float*)d_in[6];
    float* out = (float*)d_out;

    cudaFuncSetAttribute(k_main, cudaFuncAttributeMaxDynamicSharedMemorySize, SM_BYTES);

    k_detect<<<1, 256>>>((const unsigned char*)mask);
    k_cn2<<<64, 256>>>(codebook);
    k_main<<<1032, 256, SM_BYTES>>>(hidden, codebook, Win, Wout);
    k_loss<<<1, 256>>>(out, (out_size > ND) ? 1 : 0);
    k_pass2<<<8192, 256>>>(hidden, mask, gamma, beta, out);
}